// round 1
// baseline (speedup 1.0000x reference)
#include <cuda_runtime.h>

// Depthwise causal FIR conv1d, K=31.
// x: (B=8, L=4096, H=16, D=128) fp32, channel-last (C = H*D = 2048 contiguous).
// w: (H, D, K) fp32  -> per-channel taps, w[c*31 + t], out[l] = sum_t w[t]*x[l-30+t].
// y: same shape as x.
//
// Mapping: thread = (channel c, 32 consecutive l). Warp = 32 consecutive channels
// -> every global load/store is a fully coalesced 128B transaction.
// 62-element register window (32 outputs + 30 halo), fully unrolled 992 FFMAs.

#define BB 8
#define LL 4096
#define CC 2048
#define KK 31
#define TT 32
#define THREADS 128

__global__ __launch_bounds__(THREADS, 1)
void _DepthwiseFIRConv1d_kernel(const float* __restrict__ x,
                                const float* __restrict__ w,
                                float* __restrict__ y) {
    const int c  = blockIdx.x * THREADS + threadIdx.x;   // channel 0..2047
    const int l0 = blockIdx.y * TT;                      // output tile start
    const int b  = blockIdx.z;

    const float* xb = x + (b * LL) * CC + c;             // max index < 2^27 elems, int ok
    const int base = l0 - (KK - 1);                      // first window element (may be <0)

    // Front-batched window load: 62 independent LDGs -> deep MLP.
    float xv[TT + KK - 1];
#pragma unroll
    for (int i = 0; i < TT + KK - 1; i++) {
        const int l = base + i;
        xv[i] = (l >= 0) ? xb[l * CC] : 0.0f;            // causal zero-pad (only tile 0 predicates false)
    }

    float acc[TT];
#pragma unroll
    for (int j = 0; j < TT; j++) acc[j] = 0.0f;

    const float* wc = w + c * KK;
#pragma unroll
    for (int t = 0; t < KK; t++) {
        const float wt = __ldg(wc + t);                  // L1-resident after first touch
#pragma unroll
        for (int j = 0; j < TT; j++) {
            acc[j] = fmaf(wt, xv[t + j], acc[j]);
        }
    }

    float* yb = y + (b * LL + l0) * CC + c;
#pragma unroll
    for (int j = 0; j < TT; j++) {
        yb[j * CC] = acc[j];
    }
}

extern "C" void kernel_launch(void* const* d_in, const int* in_sizes, int n_in,
                              void* d_out, int out_size) {
    const float* x = (const float*)d_in[0];   // (8, 4096, 16, 128) = 67108864 floats
    const float* w = (const float*)d_in[1];   // (16, 128, 31)      = 63488 floats
    float* y = (float*)d_out;                 // (8, 4096, 16, 128)

    dim3 grid(CC / THREADS, LL / TT, BB);     // (16, 128, 8) = 16384 blocks
    _DepthwiseFIRConv1d_kernel<<<grid, THREADS>>>(x, w, y);
}